// round 10
// baseline (speedup 1.0000x reference)
#include <cuda_runtime.h>
#include <cuda_bf16.h>
#include <cuda_fp16.h>
#include <cstdint>

#define N_NODES 100000
#define N_EDGES 1600000
#define C 64

// Scratch: fp16 copy of x, fp16 aggregated features, CSR row ptrs.
__device__ __half g_xh[(size_t)N_NODES * C];
__device__ __half g_aggh[(size_t)N_NODES * C];
__device__ int g_row_ptr[N_NODES + 1];

// SW128 swizzle on byte offsets (rows of 128B): XOR bits[6:4] with bits[9:7].
#define SW(o) ((o) ^ (((o) >> 3) & 0x70))

static __device__ __forceinline__ uint32_t smem_u32(const void* p) {
    uint32_t a;
    asm("{ .reg .u64 t; cvta.to.shared.u64 t, %1; cvt.u32.u64 %0, t; }" : "=r"(a) : "l"(p));
    return a;
}
static __device__ __forceinline__ void ldsm_x4(uint32_t& r0, uint32_t& r1,
                                               uint32_t& r2, uint32_t& r3, uint32_t addr) {
    asm volatile("ldmatrix.sync.aligned.m8n8.x4.shared.b16 {%0,%1,%2,%3}, [%4];"
                 : "=r"(r0), "=r"(r1), "=r"(r2), "=r"(r3) : "r"(addr));
}
static __device__ __forceinline__ void ldsm_x4_t(uint32_t& r0, uint32_t& r1,
                                                 uint32_t& r2, uint32_t& r3, uint32_t addr) {
    asm volatile("ldmatrix.sync.aligned.m8n8.x4.trans.shared.b16 {%0,%1,%2,%3}, [%4];"
                 : "=r"(r0), "=r"(r1), "=r"(r2), "=r"(r3) : "r"(addr));
}
static __device__ __forceinline__ void mma16816(float* c, const uint32_t* a,
                                                uint32_t b0, uint32_t b1) {
    asm volatile(
        "mma.sync.aligned.m16n8k16.row.col.f32.f16.f16.f32 "
        "{%0,%1,%2,%3}, {%4,%5,%6,%7}, {%8,%9}, {%0,%1,%2,%3};"
        : "+f"(c[0]), "+f"(c[1]), "+f"(c[2]), "+f"(c[3])
        : "r"(a[0]), "r"(a[1]), "r"(a[2]), "r"(a[3]), "r"(b0), "r"(b1));
}

#define CVT_NT   (N_NODES * C / 8)            // 800000
#define CVT_B    ((CVT_NT + 255) / 256)       // 3125
#define RP_NT    (N_EDGES / 8)                // 200000
#define RP_B     ((RP_NT + 255) / 256)        // 782

// ---------------------------------------------------------------------------
// Kernel 0+1 merged: block range [0, CVT_B) converts x -> fp16 (DRAM-bound);
// block range [CVT_B, CVT_B+RP_B) fills CSR row pointers (issue-bound).
// Running them concurrently overlaps the two different bottlenecks.
// ---------------------------------------------------------------------------
__global__ __launch_bounds__(256) void prologue_kernel(const float* __restrict__ x,
                                                       const int* __restrict__ row_index) {
    if (blockIdx.x < CVT_B) {
        const int t = blockIdx.x * 256 + threadIdx.x;
        if (t >= CVT_NT) return;
        const float4* x4 = (const float4*)x;
        float4 a = __ldg(&x4[2 * t]);
        float4 b = __ldg(&x4[2 * t + 1]);
        __half2 h[4];
        h[0] = __floats2half2_rn(a.x, a.y);
        h[1] = __floats2half2_rn(a.z, a.w);
        h[2] = __floats2half2_rn(b.x, b.y);
        h[3] = __floats2half2_rn(b.z, b.w);
        ((uint4*)g_xh)[t] = *(const uint4*)h;
    } else {
        const int t = (blockIdx.x - CVT_B) * 256 + threadIdx.x;
        if (t >= RP_NT) return;

        const int4* r4 = (const int4*)row_index;
        int4 a = __ldg(&r4[2 * t]);
        int4 b = __ldg(&r4[2 * t + 1]);

        int prev = (t == 0) ? -1 : __ldg(&row_index[8 * t - 1]);
        const bool tail = (t == RP_NT - 1);

        if (b.w == prev && !tail) return;   // no boundary in this window

        int vals[8] = {a.x, a.y, a.z, a.w, b.x, b.y, b.z, b.w};
        const int ebase = 8 * t;
#pragma unroll
        for (int i = 0; i < 8; i++) {
            int cur = vals[i];
            if (cur != prev) {
                for (int n = prev + 1; n <= cur; n++) g_row_ptr[n] = ebase + i;
                prev = cur;
            }
        }
        if (tail) {
            for (int n = prev + 1; n <= N_NODES; n++) g_row_ptr[n] = N_EDGES;
        }
    }
}

// ---------------------------------------------------------------------------
// Kernel 2: segment sum of gathered fp16 x rows, fp32 accumulate, fp16 store.
// 16 lanes/node (8B per lane), 2 nodes/warp. Indices loaded as int4
// (1 L1TEX request per 4 edges instead of 4 broadcast requests).
// ---------------------------------------------------------------------------
static __device__ __forceinline__ void acc_row(float& ax, float& ay, float& az, float& aw,
                                               int src, int hl) {
    uint2 u = __ldg((const uint2*)(g_xh + (size_t)src * C) + hl);
    float2 f0 = __half22float2(*(__half2*)&u.x);
    float2 f1 = __half22float2(*(__half2*)&u.y);
    ax += f0.x; ay += f0.y; az += f1.x; aw += f1.y;
}

__global__ __launch_bounds__(256) void agg_kernel(const int* __restrict__ column_index) {
    const int warp = (blockIdx.x * blockDim.x + threadIdx.x) >> 5;
    const int lane = threadIdx.x & 31;
    const int half = lane >> 4;
    const int hl = lane & 15;
    const int node = warp * 2 + half;
    if (node >= N_NODES) return;

    const int start = g_row_ptr[node];
    const int end = g_row_ptr[node + 1];

    float ax = 0.f, ay = 0.f, az = 0.f, aw = 0.f;

    int e = start;
    // head: advance to int4 alignment
    while (e < end && (e & 3)) {
        acc_row(ax, ay, az, aw, __ldg(&column_index[e]), hl);
        e++;
    }
    // body: int4 index loads (broadcast, 1 request per 4 edges)
    for (; e + 3 < end; e += 4) {
        int4 s = __ldg((const int4*)(column_index + e));
        acc_row(ax, ay, az, aw, s.x, hl);
        acc_row(ax, ay, az, aw, s.y, hl);
        acc_row(ax, ay, az, aw, s.z, hl);
        acc_row(ax, ay, az, aw, s.w, hl);
    }
    // tail
    for (; e < end; e++) {
        acc_row(ax, ay, az, aw, __ldg(&column_index[e]), hl);
    }

    __half2 h0 = __floats2half2_rn(ax, ay);
    __half2 h1 = __floats2half2_rn(az, aw);
    ((uint2*)(g_aggh + (size_t)node * C))[hl] =
        make_uint2(*(uint32_t*)&h0, *(uint32_t*)&h1);
}

// ---------------------------------------------------------------------------
// Kernel 3: out = (g_aggh @ W) * deg[row] + bias  — fp16 HMMA, fp32 accumulate.
// 256 threads (8 warps), 128-row tile; each warp computes 16 rows x 64 cols.
// SW128-swizzled smem + ldmatrix, conflict-free.
// ---------------------------------------------------------------------------
__global__ __launch_bounds__(256) void gemm_mma_kernel(const float* __restrict__ w,
                                                       const float* __restrict__ bias,
                                                       const float* __restrict__ degrees,
                                                       float* __restrict__ out) {
    __shared__ __align__(128) __half As[128 * 64];   // 16 KB
    __shared__ __align__(128) __half Ws[64 * 64];    // 8 KB

    const int tid = threadIdx.x;
    const int wid = tid >> 5;        // 0..7
    const int lane = tid & 31;
    const long row0 = (long)blockIdx.x * 128;

    // --- Load W (fp32 -> fp16), swizzled. 1024 float4 chunks over 256 threads.
    {
        const float4* w4 = (const float4*)w;
        char* wsb = (char*)Ws;
#pragma unroll
        for (int i = 0; i < 4; i++) {
            int ch = i * 256 + tid;          // 0..1023
            int k = ch >> 4, n4 = ch & 15;
            float4 v = __ldg(&w4[ch]);
            __half2 h0 = __floats2half2_rn(v.x, v.y);
            __half2 h1 = __floats2half2_rn(v.z, v.w);
            uint2 pk = make_uint2(*(uint32_t*)&h0, *(uint32_t*)&h1);
            *(uint2*)(wsb + SW(k * 128 + n4 * 8)) = pk;
        }
    }

    // --- Load A tile (fp16 agg rows), swizzled. 1024 uint4 chunks.
    {
        const uint4* a4 = (const uint4*)g_aggh;
        char* asb = (char*)As;
#pragma unroll
        for (int i = 0; i < 4; i++) {
            int ch = i * 256 + tid;          // 0..1023
            int r = ch >> 3, cg = ch & 7;
            long gr = row0 + r;
            uint4 v = make_uint4(0u, 0u, 0u, 0u);
            if (gr < N_NODES) v = __ldg(&a4[gr * 8 + cg]);
            *(uint4*)(asb + SW(r * 128 + cg * 16)) = v;
        }
    }
    __syncthreads();

    const uint32_t as_base = smem_u32(As);
    const uint32_t ws_base = smem_u32(Ws);
    const int wrow = wid * 16;
    const int lr = lane & 15;
    const int lc = lane >> 4;

    float c[8][4];
#pragma unroll
    for (int nt = 0; nt < 8; nt++)
#pragma unroll
        for (int j = 0; j < 4; j++) c[nt][j] = 0.f;

#pragma unroll
    for (int kc = 0; kc < 4; kc++) {
        uint32_t a[4];
        {
            uint32_t addr = as_base + SW((wrow + lr) * 128 + kc * 32 + lc * 16);
            ldsm_x4(a[0], a[1], a[2], a[3], addr);
        }
#pragma unroll
        for (int np = 0; np < 4; np++) {
            uint32_t b0, b1, b2, b3;
            uint32_t addr = ws_base +
                SW((kc * 16 + lr) * 128 + (np * 16 + lc * 8) * 2);
            ldsm_x4_t(b0, b1, b2, b3, addr);
            mma16816(c[2 * np], a, b0, b1);
            mma16816(c[2 * np + 1], a, b2, b3);
        }
    }

    // --- Epilogue: o = c * deg[row] + bias[col], direct float2 stores.
    const int qr = lane >> 2;
    const int qc = (lane & 3) * 2;
    float2 bv[8];
#pragma unroll
    for (int nt = 0; nt < 8; nt++)
        bv[nt] = __ldg((const float2*)(bias + nt * 8 + qc));

    long rlo = row0 + wrow + qr;
    long rhi = rlo + 8;
    float dlo = (rlo < N_NODES) ? __ldg(&degrees[rlo]) : 0.f;
    float dhi = (rhi < N_NODES) ? __ldg(&degrees[rhi]) : 0.f;
#pragma unroll
    for (int nt = 0; nt < 8; nt++) {
        if (rlo < N_NODES) {
            float2 o;
            o.x = c[nt][0] * dlo + bv[nt].x;
            o.y = c[nt][1] * dlo + bv[nt].y;
            *(float2*)(out + (size_t)rlo * C + nt * 8 + qc) = o;
        }
        if (rhi < N_NODES) {
            float2 o;
            o.x = c[nt][2] * dhi + bv[nt].x;
            o.y = c[nt][3] * dhi + bv[nt].y;
            *(float2*)(out + (size_t)rhi * C + nt * 8 + qc) = o;
        }
    }
}

// ---------------------------------------------------------------------------
extern "C" void kernel_launch(void* const* d_in, const int* in_sizes, int n_in,
                              void* d_out, int out_size) {
    const float* x            = (const float*)d_in[0];   // [N_NODES, 64]
    const float* weight       = (const float*)d_in[1];   // [64, 64]
    const float* bias         = (const float*)d_in[2];   // [64]
    const int*   column_index = (const int*)d_in[3];     // [N_EDGES]
    const int*   row_index    = (const int*)d_in[4];     // [N_EDGES] sorted
    const float* degrees      = (const float*)d_in[5];   // [N_NODES]
    float* out = (float*)d_out;                          // [N_NODES, 64]

    // 0) fp16 copy of x + CSR row pointers, overlapped in one launch
    prologue_kernel<<<CVT_B + RP_B, 256>>>(x, row_index);

    // 1) agg = segment_sum(xh[col]) -> fp16
    const int warps = (N_NODES + 1) / 2;
    agg_kernel<<<(warps * 32 + 255) / 256, 256>>>(column_index);

    // 2) out = (agg @ W) * deg + bias   (HMMA)
    gemm_mma_kernel<<<(N_NODES + 127) / 128, 256>>>(weight, bias, degrees, out);
}

// round 11
// speedup vs baseline: 1.1544x; 1.1544x over previous
#include <cuda_runtime.h>
#include <cuda_bf16.h>
#include <cuda_fp16.h>
#include <cstdint>

#define N_NODES 100000
#define N_EDGES 1600000
#define C 64

// Scratch: fp16 transformed features h = x @ W, CSR row ptrs.
__device__ __half g_h[(size_t)N_NODES * C];
__device__ int g_row_ptr[N_NODES + 1];

// SW128 swizzle on byte offsets (rows of 128B): XOR bits[6:4] with bits[9:7].
#define SW(o) ((o) ^ (((o) >> 3) & 0x70))

static __device__ __forceinline__ uint32_t smem_u32(const void* p) {
    uint32_t a;
    asm("{ .reg .u64 t; cvta.to.shared.u64 t, %1; cvt.u32.u64 %0, t; }" : "=r"(a) : "l"(p));
    return a;
}
static __device__ __forceinline__ void ldsm_x4(uint32_t& r0, uint32_t& r1,
                                               uint32_t& r2, uint32_t& r3, uint32_t addr) {
    asm volatile("ldmatrix.sync.aligned.m8n8.x4.shared.b16 {%0,%1,%2,%3}, [%4];"
                 : "=r"(r0), "=r"(r1), "=r"(r2), "=r"(r3) : "r"(addr));
}
static __device__ __forceinline__ void ldsm_x4_t(uint32_t& r0, uint32_t& r1,
                                                 uint32_t& r2, uint32_t& r3, uint32_t addr) {
    asm volatile("ldmatrix.sync.aligned.m8n8.x4.trans.shared.b16 {%0,%1,%2,%3}, [%4];"
                 : "=r"(r0), "=r"(r1), "=r"(r2), "=r"(r3) : "r"(addr));
}
static __device__ __forceinline__ void mma16816(float* c, const uint32_t* a,
                                                uint32_t b0, uint32_t b1) {
    asm volatile(
        "mma.sync.aligned.m16n8k16.row.col.f32.f16.f16.f32 "
        "{%0,%1,%2,%3}, {%4,%5,%6,%7}, {%8,%9}, {%0,%1,%2,%3};"
        : "+f"(c[0]), "+f"(c[1]), "+f"(c[2]), "+f"(c[3])
        : "r"(a[0]), "r"(a[1]), "r"(a[2]), "r"(a[3]), "r"(b0), "r"(b1));
}

#define RP_NT    (N_EDGES / 8)                // 200000
#define RP_B     ((RP_NT + 255) / 256)        // 782
#define GEMM_B   ((N_NODES + 127) / 128)      // 782

// ---------------------------------------------------------------------------
// Kernel A (merged): blocks [0, RP_B) fill CSR row pointers (issue-bound);
// blocks [RP_B, RP_B+GEMM_B) compute h = (x @ W) in fp16 via HMMA
// (DRAM-bound: 25.6 MB read + 12.8 MB write). The two parts overlap.
// ---------------------------------------------------------------------------
__global__ __launch_bounds__(256) void transform_kernel(const float* __restrict__ x,
                                                        const float* __restrict__ w,
                                                        const int* __restrict__ row_index) {
    __shared__ __align__(128) __half As[128 * 64];   // 16 KB x tile (fp16)
    __shared__ __align__(128) __half Ws[64 * 64];    // 8 KB  W (fp16)

    if (blockIdx.x < RP_B) {
        // ----- CSR row pointer fill, 8 edges/thread, fast-skip -----
        const int t = blockIdx.x * 256 + threadIdx.x;
        if (t >= RP_NT) return;

        const int4* r4 = (const int4*)row_index;
        int4 a = __ldg(&r4[2 * t]);
        int4 b = __ldg(&r4[2 * t + 1]);

        int prev = (t == 0) ? -1 : __ldg(&row_index[8 * t - 1]);
        const bool tail = (t == RP_NT - 1);

        if (b.w == prev && !tail) return;

        int vals[8] = {a.x, a.y, a.z, a.w, b.x, b.y, b.z, b.w};
        const int ebase = 8 * t;
#pragma unroll
        for (int i = 0; i < 8; i++) {
            int cur = vals[i];
            if (cur != prev) {
                for (int n = prev + 1; n <= cur; n++) g_row_ptr[n] = ebase + i;
                prev = cur;
            }
        }
        if (tail) {
            for (int n = prev + 1; n <= N_NODES; n++) g_row_ptr[n] = N_EDGES;
        }
        return;
    }

    // ----- h = x @ W (fp16 HMMA, fp32 accumulate, fp16 store) -----
    const int bid = blockIdx.x - RP_B;
    const int tid = threadIdx.x;
    const int wid = tid >> 5;        // 0..7
    const int lane = tid & 31;
    const long row0 = (long)bid * 128;

    // Load W (fp32 -> fp16), swizzled. 1024 float4 chunks over 256 threads.
    {
        const float4* w4 = (const float4*)w;
        char* wsb = (char*)Ws;
#pragma unroll
        for (int i = 0; i < 4; i++) {
            int ch = i * 256 + tid;          // 0..1023
            int k = ch >> 4, n4 = ch & 15;
            float4 v = __ldg(&w4[ch]);
            __half2 h0 = __floats2half2_rn(v.x, v.y);
            __half2 h1 = __floats2half2_rn(v.z, v.w);
            uint2 pk = make_uint2(*(uint32_t*)&h0, *(uint32_t*)&h1);
            *(uint2*)(wsb + SW(k * 128 + n4 * 8)) = pk;
        }
    }

    // Load x tile (fp32 -> fp16), swizzled. 2048 float4 chunks.
    {
        const float4* x4 = (const float4*)x;
        char* asb = (char*)As;
#pragma unroll
        for (int i = 0; i < 8; i++) {
            int ch = i * 256 + tid;          // 0..2047
            int r = ch >> 4, c4 = ch & 15;
            long gr = row0 + r;
            float4 v = make_float4(0.f, 0.f, 0.f, 0.f);
            if (gr < N_NODES) v = __ldg(&x4[gr * 16 + c4]);
            __half2 h0 = __floats2half2_rn(v.x, v.y);
            __half2 h1 = __floats2half2_rn(v.z, v.w);
            uint2 pk = make_uint2(*(uint32_t*)&h0, *(uint32_t*)&h1);
            *(uint2*)(asb + SW(r * 128 + c4 * 8)) = pk;
        }
    }
    __syncthreads();

    const uint32_t as_base = smem_u32(As);
    const uint32_t ws_base = smem_u32(Ws);
    const int wrow = wid * 16;
    const int lr = lane & 15;
    const int lc = lane >> 4;

    float c[8][4];
#pragma unroll
    for (int nt = 0; nt < 8; nt++)
#pragma unroll
        for (int j = 0; j < 4; j++) c[nt][j] = 0.f;

#pragma unroll
    for (int kc = 0; kc < 4; kc++) {
        uint32_t a[4];
        {
            uint32_t addr = as_base + SW((wrow + lr) * 128 + kc * 32 + lc * 16);
            ldsm_x4(a[0], a[1], a[2], a[3], addr);
        }
#pragma unroll
        for (int np = 0; np < 4; np++) {
            uint32_t b0, b1, b2, b3;
            uint32_t addr = ws_base +
                SW((kc * 16 + lr) * 128 + (np * 16 + lc * 8) * 2);
            ldsm_x4_t(b0, b1, b2, b3, addr);
            mma16816(c[2 * np], a, b0, b1);
            mma16816(c[2 * np + 1], a, b2, b3);
        }
    }

    // Epilogue: store h as fp16 (half2 per fragment pair).
    const int qr = lane >> 2;
    const int qc = (lane & 3) * 2;
    long rlo = row0 + wrow + qr;
    long rhi = rlo + 8;
#pragma unroll
    for (int nt = 0; nt < 8; nt++) {
        if (rlo < N_NODES) {
            __half2 h = __floats2half2_rn(c[nt][0], c[nt][1]);
            *(__half2*)(g_h + (size_t)rlo * C + nt * 8 + qc) = h;
        }
        if (rhi < N_NODES) {
            __half2 h = __floats2half2_rn(c[nt][2], c[nt][3]);
            *(__half2*)(g_h + (size_t)rhi * C + nt * 8 + qc) = h;
        }
    }
}

// ---------------------------------------------------------------------------
// Kernel B: out = segment_sum(h[col]) * deg + bias.
// fp16 gather (128 B/edge), fp32 accumulate, fp32 out.
// 16 lanes/node (8B = 4 halves per lane), 2 nodes/warp, no atomics.
// ---------------------------------------------------------------------------
static __device__ __forceinline__ void acc_row(float& ax, float& ay, float& az, float& aw,
                                               int src, int hl) {
    uint2 u = __ldg((const uint2*)(g_h + (size_t)src * C) + hl);
    float2 f0 = __half22float2(*(__half2*)&u.x);
    float2 f1 = __half22float2(*(__half2*)&u.y);
    ax += f0.x; ay += f0.y; az += f1.x; aw += f1.y;
}

__global__ __launch_bounds__(256) void agg_kernel(const int* __restrict__ column_index,
                                                  const float* __restrict__ degrees,
                                                  const float* __restrict__ bias,
                                                  float* __restrict__ out) {
    const int warp = (blockIdx.x * blockDim.x + threadIdx.x) >> 5;
    const int lane = threadIdx.x & 31;
    const int half = lane >> 4;
    const int hl = lane & 15;
    const int node = warp * 2 + half;
    if (node >= N_NODES) return;

    const int start = g_row_ptr[node];
    const int end = g_row_ptr[node + 1];

    float ax = 0.f, ay = 0.f, az = 0.f, aw = 0.f;

    int e = start;
    for (; e + 3 < end; e += 4) {
        int s0 = __ldg(&column_index[e]);
        int s1 = __ldg(&column_index[e + 1]);
        int s2 = __ldg(&column_index[e + 2]);
        int s3 = __ldg(&column_index[e + 3]);
        acc_row(ax, ay, az, aw, s0, hl);
        acc_row(ax, ay, az, aw, s1, hl);
        acc_row(ax, ay, az, aw, s2, hl);
        acc_row(ax, ay, az, aw, s3, hl);
    }
    for (; e < end; e++) {
        acc_row(ax, ay, az, aw, __ldg(&column_index[e]), hl);
    }

    const float d = __ldg(&degrees[node]);
    const float4 b = __ldg((const float4*)bias + hl);
    float4 o;
    o.x = ax * d + b.x;
    o.y = ay * d + b.y;
    o.z = az * d + b.z;
    o.w = aw * d + b.w;
    ((float4*)(out + (size_t)node * C))[hl] = o;
}

// ---------------------------------------------------------------------------
extern "C" void kernel_launch(void* const* d_in, const int* in_sizes, int n_in,
                              void* d_out, int out_size) {
    const float* x            = (const float*)d_in[0];   // [N_NODES, 64]
    const float* weight       = (const float*)d_in[1];   // [64, 64]
    const float* bias         = (const float*)d_in[2];   // [64]
    const int*   column_index = (const int*)d_in[3];     // [N_EDGES]
    const int*   row_index    = (const int*)d_in[4];     // [N_EDGES] sorted
    const float* degrees      = (const float*)d_in[5];   // [N_NODES]
    float* out = (float*)d_out;                          // [N_NODES, 64]

    // A) h = x @ W (fp16, HMMA) overlapped with CSR row-pointer fill
    transform_kernel<<<RP_B + GEMM_B, 256>>>(x, weight, row_index);

    // B) out = segment_sum(h[col]) * deg + bias
    const int warps = (N_NODES + 1) / 2;
    agg_kernel<<<(warps * 32 + 255) / 256, 256>>>(column_index, degrees, bias, out);
}

// round 12
// speedup vs baseline: 1.2264x; 1.0623x over previous
#include <cuda_runtime.h>
#include <cuda_bf16.h>
#include <cuda_fp16.h>
#include <cstdint>

#define N_NODES 100000
#define N_EDGES 1600000
#define C 64

// Scratch: fp16 transformed features h = x @ W, CSR row ptrs.
__device__ __half g_h[(size_t)N_NODES * C];
__device__ int g_row_ptr[N_NODES + 1];

// SW128 swizzle on byte offsets (rows of 128B): XOR bits[6:4] with bits[9:7].
#define SW(o) ((o) ^ (((o) >> 3) & 0x70))

static __device__ __forceinline__ uint32_t smem_u32(const void* p) {
    uint32_t a;
    asm("{ .reg .u64 t; cvta.to.shared.u64 t, %1; cvt.u32.u64 %0, t; }" : "=r"(a) : "l"(p));
    return a;
}
static __device__ __forceinline__ void ldsm_x4(uint32_t& r0, uint32_t& r1,
                                               uint32_t& r2, uint32_t& r3, uint32_t addr) {
    asm volatile("ldmatrix.sync.aligned.m8n8.x4.shared.b16 {%0,%1,%2,%3}, [%4];"
                 : "=r"(r0), "=r"(r1), "=r"(r2), "=r"(r3) : "r"(addr));
}
static __device__ __forceinline__ void ldsm_x4_t(uint32_t& r0, uint32_t& r1,
                                                 uint32_t& r2, uint32_t& r3, uint32_t addr) {
    asm volatile("ldmatrix.sync.aligned.m8n8.x4.trans.shared.b16 {%0,%1,%2,%3}, [%4];"
                 : "=r"(r0), "=r"(r1), "=r"(r2), "=r"(r3) : "r"(addr));
}
static __device__ __forceinline__ void mma16816(float* c, const uint32_t* a,
                                                uint32_t b0, uint32_t b1) {
    asm volatile(
        "mma.sync.aligned.m16n8k16.row.col.f32.f16.f16.f32 "
        "{%0,%1,%2,%3}, {%4,%5,%6,%7}, {%8,%9}, {%0,%1,%2,%3};"
        : "+f"(c[0]), "+f"(c[1]), "+f"(c[2]), "+f"(c[3])
        : "r"(a[0]), "r"(a[1]), "r"(a[2]), "r"(a[3]), "r"(b0), "r"(b1));
}

#define RP_NT    (N_EDGES / 8)                // 200000
#define RP_B     ((RP_NT + 255) / 256)        // 782
#define GEMM_B   ((N_NODES + 127) / 128)      // 782

// ---------------------------------------------------------------------------
// Kernel A (merged): blocks [0, RP_B) fill CSR row pointers (issue-bound);
// blocks [RP_B, RP_B+GEMM_B) compute h = (x @ W) in fp16 via HMMA
// (DRAM-bound: 25.6 MB read + 12.8 MB write). The two parts overlap.
// ---------------------------------------------------------------------------
__global__ __launch_bounds__(256) void transform_kernel(const float* __restrict__ x,
                                                        const float* __restrict__ w,
                                                        const int* __restrict__ row_index) {
    __shared__ __align__(128) __half As[128 * 64];   // 16 KB x tile (fp16)
    __shared__ __align__(128) __half Ws[64 * 64];    // 8 KB  W (fp16)

    if (blockIdx.x < RP_B) {
        // ----- CSR row pointer fill, 8 edges/thread, fast-skip -----
        const int t = blockIdx.x * 256 + threadIdx.x;
        if (t >= RP_NT) return;

        const int4* r4 = (const int4*)row_index;
        int4 a = __ldg(&r4[2 * t]);
        int4 b = __ldg(&r4[2 * t + 1]);

        int prev = (t == 0) ? -1 : __ldg(&row_index[8 * t - 1]);
        const bool tail = (t == RP_NT - 1);

        if (b.w == prev && !tail) return;

        int vals[8] = {a.x, a.y, a.z, a.w, b.x, b.y, b.z, b.w};
        const int ebase = 8 * t;
#pragma unroll
        for (int i = 0; i < 8; i++) {
            int cur = vals[i];
            if (cur != prev) {
                for (int n = prev + 1; n <= cur; n++) g_row_ptr[n] = ebase + i;
                prev = cur;
            }
        }
        if (tail) {
            for (int n = prev + 1; n <= N_NODES; n++) g_row_ptr[n] = N_EDGES;
        }
        return;
    }

    // ----- h = x @ W (fp16 HMMA, fp32 accumulate, fp16 store) -----
    const int bid = blockIdx.x - RP_B;
    const int tid = threadIdx.x;
    const int wid = tid >> 5;        // 0..7
    const int lane = tid & 31;
    const long row0 = (long)bid * 128;

    // Load W (fp32 -> fp16), swizzled. 1024 float4 chunks over 256 threads.
    {
        const float4* w4 = (const float4*)w;
        char* wsb = (char*)Ws;
#pragma unroll
        for (int i = 0; i < 4; i++) {
            int ch = i * 256 + tid;          // 0..1023
            int k = ch >> 4, n4 = ch & 15;
            float4 v = __ldg(&w4[ch]);
            __half2 h0 = __floats2half2_rn(v.x, v.y);
            __half2 h1 = __floats2half2_rn(v.z, v.w);
            uint2 pk = make_uint2(*(uint32_t*)&h0, *(uint32_t*)&h1);
            *(uint2*)(wsb + SW(k * 128 + n4 * 8)) = pk;
        }
    }

    // Load x tile (fp32 -> fp16), swizzled. 2048 float4 chunks.
    {
        const float4* x4 = (const float4*)x;
        char* asb = (char*)As;
#pragma unroll
        for (int i = 0; i < 8; i++) {
            int ch = i * 256 + tid;          // 0..2047
            int r = ch >> 4, c4 = ch & 15;
            long gr = row0 + r;
            float4 v = make_float4(0.f, 0.f, 0.f, 0.f);
            if (gr < N_NODES) v = __ldg(&x4[gr * 16 + c4]);
            __half2 h0 = __floats2half2_rn(v.x, v.y);
            __half2 h1 = __floats2half2_rn(v.z, v.w);
            uint2 pk = make_uint2(*(uint32_t*)&h0, *(uint32_t*)&h1);
            *(uint2*)(asb + SW(r * 128 + c4 * 8)) = pk;
        }
    }
    __syncthreads();

    const uint32_t as_base = smem_u32(As);
    const uint32_t ws_base = smem_u32(Ws);
    const int wrow = wid * 16;
    const int lr = lane & 15;
    const int lc = lane >> 4;

    float c[8][4];
#pragma unroll
    for (int nt = 0; nt < 8; nt++)
#pragma unroll
        for (int j = 0; j < 4; j++) c[nt][j] = 0.f;

#pragma unroll
    for (int kc = 0; kc < 4; kc++) {
        uint32_t a[4];
        {
            uint32_t addr = as_base + SW((wrow + lr) * 128 + kc * 32 + lc * 16);
            ldsm_x4(a[0], a[1], a[2], a[3], addr);
        }
#pragma unroll
        for (int np = 0; np < 4; np++) {
            uint32_t b0, b1, b2, b3;
            uint32_t addr = ws_base +
                SW((kc * 16 + lr) * 128 + (np * 16 + lc * 8) * 2);
            ldsm_x4_t(b0, b1, b2, b3, addr);
            mma16816(c[2 * np], a, b0, b1);
            mma16816(c[2 * np + 1], a, b2, b3);
        }
    }

    // Epilogue: store h as fp16 (half2 per fragment pair).
    const int qr = lane >> 2;
    const int qc = (lane & 3) * 2;
    long rlo = row0 + wrow + qr;
    long rhi = rlo + 8;
#pragma unroll
    for (int nt = 0; nt < 8; nt++) {
        if (rlo < N_NODES) {
            __half2 h = __floats2half2_rn(c[nt][0], c[nt][1]);
            *(__half2*)(g_h + (size_t)rlo * C + nt * 8 + qc) = h;
        }
        if (rhi < N_NODES) {
            __half2 h = __floats2half2_rn(c[nt][2], c[nt][3]);
            *(__half2*)(g_h + (size_t)rhi * C + nt * 8 + qc) = h;
        }
    }
}

// ---------------------------------------------------------------------------
// Kernel B: out = segment_sum(h[col]) * deg + bias.
// fp16 gather (128 B/edge), depth-2 fp16 pairwise tree per 4-edge group
// (6 HADD2 instead of 8 F2F + 16 FADD), fp32 accumulation across groups.
// 16 lanes/node (8B = 4 halves per lane), 2 nodes/warp, no atomics.
// ---------------------------------------------------------------------------
__global__ __launch_bounds__(256) void agg_kernel(const int* __restrict__ column_index,
                                                  const float* __restrict__ degrees,
                                                  const float* __restrict__ bias,
                                                  float* __restrict__ out) {
    const int warp = (blockIdx.x * blockDim.x + threadIdx.x) >> 5;
    const int lane = threadIdx.x & 31;
    const int half = lane >> 4;
    const int hl = lane & 15;
    const int node = warp * 2 + half;
    if (node >= N_NODES) return;

    const int start = g_row_ptr[node];
    const int end = g_row_ptr[node + 1];

    float ax = 0.f, ay = 0.f, az = 0.f, aw = 0.f;

    const uint2* hrow;
    int e = start;
    // body: 4-edge groups, fp16 pairwise tree then one fp32 flush
    for (; e + 3 < end; e += 4) {
        int s0 = __ldg(&column_index[e]);
        int s1 = __ldg(&column_index[e + 1]);
        int s2 = __ldg(&column_index[e + 2]);
        int s3 = __ldg(&column_index[e + 3]);
        uint2 u0 = __ldg((const uint2*)(g_h + (size_t)s0 * C) + hl);
        uint2 u1 = __ldg((const uint2*)(g_h + (size_t)s1 * C) + hl);
        uint2 u2 = __ldg((const uint2*)(g_h + (size_t)s2 * C) + hl);
        uint2 u3 = __ldg((const uint2*)(g_h + (size_t)s3 * C) + hl);
        // level 1
        __half2 p0 = __hadd2(*(__half2*)&u0.x, *(__half2*)&u1.x);
        __half2 p1 = __hadd2(*(__half2*)&u0.y, *(__half2*)&u1.y);
        __half2 q0 = __hadd2(*(__half2*)&u2.x, *(__half2*)&u3.x);
        __half2 q1 = __hadd2(*(__half2*)&u2.y, *(__half2*)&u3.y);
        // level 2
        __half2 t0 = __hadd2(p0, q0);
        __half2 t1 = __hadd2(p1, q1);
        // flush to fp32
        float2 f0 = __half22float2(t0);
        float2 f1 = __half22float2(t1);
        ax += f0.x; ay += f0.y; az += f1.x; aw += f1.y;
    }
    // tail: exact fp32 path
    for (; e < end; e++) {
        int s0 = __ldg(&column_index[e]);
        uint2 u = __ldg((const uint2*)(g_h + (size_t)s0 * C) + hl);
        float2 f0 = __half22float2(*(__half2*)&u.x);
        float2 f1 = __half22float2(*(__half2*)&u.y);
        ax += f0.x; ay += f0.y; az += f1.x; aw += f1.y;
    }
    (void)hrow;

    const float d = __ldg(&degrees[node]);
    const float4 b = __ldg((const float4*)bias + hl);
    float4 o;
    o.x = ax * d + b.x;
    o.y = ay * d + b.y;
    o.z = az * d + b.z;
    o.w = aw * d + b.w;
    ((float4*)(out + (size_t)node * C))[hl] = o;
}

// ---------------------------------------------------------------------------
extern "C" void kernel_launch(void* const* d_in, const int* in_sizes, int n_in,
                              void* d_out, int out_size) {
    const float* x            = (const float*)d_in[0];   // [N_NODES, 64]
    const float* weight       = (const float*)d_in[1];   // [64, 64]
    const float* bias         = (const float*)d_in[2];   // [64]
    const int*   column_index = (const int*)d_in[3];     // [N_EDGES]
    const int*   row_index    = (const int*)d_in[4];     // [N_EDGES] sorted
    const float* degrees      = (const float*)d_in[5];   // [N_NODES]
    float* out = (float*)d_out;                          // [N_NODES, 64]

    // A) h = x @ W (fp16, HMMA) overlapped with CSR row-pointer fill
    transform_kernel<<<RP_B + GEMM_B, 256>>>(x, weight, row_index);

    // B) out = segment_sum(h[col]) * deg + bias
    const int warps = (N_NODES + 1) / 2;
    agg_kernel<<<(warps * 32 + 255) / 256, 256>>>(column_index, degrees, bias, out);
}

// round 13
// speedup vs baseline: 1.2800x; 1.0437x over previous
#include <cuda_runtime.h>
#include <cuda_bf16.h>
#include <cuda_fp16.h>
#include <cstdint>

#define N_NODES 100000
#define N_EDGES 1600000
#define C 64

// Scratch: fp16 transformed features h = x @ W, CSR row ptrs.
__device__ __half g_h[(size_t)N_NODES * C];
__device__ int g_row_ptr[N_NODES + 1];

// SW128 swizzle on byte offsets (rows of 128B): XOR bits[6:4] with bits[9:7].
#define SW(o) ((o) ^ (((o) >> 3) & 0x70))

static __device__ __forceinline__ uint32_t smem_u32(const void* p) {
    uint32_t a;
    asm("{ .reg .u64 t; cvta.to.shared.u64 t, %1; cvt.u32.u64 %0, t; }" : "=r"(a) : "l"(p));
    return a;
}
static __device__ __forceinline__ void ldsm_x4(uint32_t& r0, uint32_t& r1,
                                               uint32_t& r2, uint32_t& r3, uint32_t addr) {
    asm volatile("ldmatrix.sync.aligned.m8n8.x4.shared.b16 {%0,%1,%2,%3}, [%4];"
                 : "=r"(r0), "=r"(r1), "=r"(r2), "=r"(r3) : "r"(addr));
}
static __device__ __forceinline__ void ldsm_x4_t(uint32_t& r0, uint32_t& r1,
                                                 uint32_t& r2, uint32_t& r3, uint32_t addr) {
    asm volatile("ldmatrix.sync.aligned.m8n8.x4.trans.shared.b16 {%0,%1,%2,%3}, [%4];"
                 : "=r"(r0), "=r"(r1), "=r"(r2), "=r"(r3) : "r"(addr));
}
static __device__ __forceinline__ void mma16816(float* c, const uint32_t* a,
                                                uint32_t b0, uint32_t b1) {
    asm volatile(
        "mma.sync.aligned.m16n8k16.row.col.f32.f16.f16.f32 "
        "{%0,%1,%2,%3}, {%4,%5,%6,%7}, {%8,%9}, {%0,%1,%2,%3};"
        : "+f"(c[0]), "+f"(c[1]), "+f"(c[2]), "+f"(c[3])
        : "r"(a[0]), "r"(a[1]), "r"(a[2]), "r"(a[3]), "r"(b0), "r"(b1));
}

#define RP_NT    (N_EDGES / 8)                // 200000
#define RP_B     ((RP_NT + 255) / 256)        // 782
#define GEMM_B   ((N_NODES + 63) / 64)        // 1563 (64-row tiles)

// ---------------------------------------------------------------------------
// Kernel A (merged): blocks [0, RP_B) fill CSR row pointers (issue-bound);
// blocks [RP_B, RP_B+GEMM_B) compute h = (x @ W) in fp16 via HMMA with
// 64-row tiles (1563 blocks -> better DRAM phase overlap).
// ---------------------------------------------------------------------------
__global__ __launch_bounds__(256) void transform_kernel(const float* __restrict__ x,
                                                        const float* __restrict__ w,
                                                        const int* __restrict__ row_index) {
    __shared__ __align__(128) __half As[64 * 64];    // 8 KB x tile (fp16)
    __shared__ __align__(128) __half Ws[64 * 64];    // 8 KB W (fp16)

    if (blockIdx.x < RP_B) {
        // ----- CSR row pointer fill, 8 edges/thread, fast-skip -----
        const int t = blockIdx.x * 256 + threadIdx.x;
        if (t >= RP_NT) return;

        const int4* r4 = (const int4*)row_index;
        int4 a = __ldg(&r4[2 * t]);
        int4 b = __ldg(&r4[2 * t + 1]);

        int prev = (t == 0) ? -1 : __ldg(&row_index[8 * t - 1]);
        const bool tail = (t == RP_NT - 1);

        if (b.w == prev && !tail) return;

        int vals[8] = {a.x, a.y, a.z, a.w, b.x, b.y, b.z, b.w};
        const int ebase = 8 * t;
#pragma unroll
        for (int i = 0; i < 8; i++) {
            int cur = vals[i];
            if (cur != prev) {
                for (int n = prev + 1; n <= cur; n++) g_row_ptr[n] = ebase + i;
                prev = cur;
            }
        }
        if (tail) {
            for (int n = prev + 1; n <= N_NODES; n++) g_row_ptr[n] = N_EDGES;
        }
        return;
    }

    // ----- h = x @ W (fp16 HMMA, fp32 accumulate, fp16 store), 64-row tile --
    const int bid = blockIdx.x - RP_B;
    const int tid = threadIdx.x;
    const int wid = tid >> 5;        // 0..7
    const int lane = tid & 31;
    const long row0 = (long)bid * 64;

    // Load W (fp32 -> fp16), swizzled. 1024 float4 chunks over 256 threads.
    {
        const float4* w4 = (const float4*)w;
        char* wsb = (char*)Ws;
#pragma unroll
        for (int i = 0; i < 4; i++) {
            int ch = i * 256 + tid;          // 0..1023
            int k = ch >> 4, n4 = ch & 15;
            float4 v = __ldg(&w4[ch]);
            __half2 h0 = __floats2half2_rn(v.x, v.y);
            __half2 h1 = __floats2half2_rn(v.z, v.w);
            uint2 pk = make_uint2(*(uint32_t*)&h0, *(uint32_t*)&h1);
            *(uint2*)(wsb + SW(k * 128 + n4 * 8)) = pk;
        }
    }

    // Load x tile (fp32 -> fp16), swizzled. 1024 float4 chunks (64 rows).
    {
        const float4* x4 = (const float4*)x;
        char* asb = (char*)As;
#pragma unroll
        for (int i = 0; i < 4; i++) {
            int ch = i * 256 + tid;          // 0..1023
            int r = ch >> 4, c4 = ch & 15;
            long gr = row0 + r;
            float4 v = make_float4(0.f, 0.f, 0.f, 0.f);
            if (gr < N_NODES) v = __ldg(&x4[gr * 16 + c4]);
            __half2 h0 = __floats2half2_rn(v.x, v.y);
            __half2 h1 = __floats2half2_rn(v.z, v.w);
            uint2 pk = make_uint2(*(uint32_t*)&h0, *(uint32_t*)&h1);
            *(uint2*)(asb + SW(r * 128 + c4 * 8)) = pk;
        }
    }
    __syncthreads();

    const uint32_t as_base = smem_u32(As);
    const uint32_t ws_base = smem_u32(Ws);
    const int rg = wid & 3;          // 16-row group 0..3
    const int chalf = wid >> 2;      // 32-col half 0..1
    const int lr = lane & 15;
    const int lc = lane >> 4;

    float c[4][4];
#pragma unroll
    for (int nt = 0; nt < 4; nt++)
#pragma unroll
        for (int j = 0; j < 4; j++) c[nt][j] = 0.f;

#pragma unroll
    for (int kc = 0; kc < 4; kc++) {
        uint32_t a[4];
        {
            uint32_t addr = as_base + SW((rg * 16 + lr) * 128 + kc * 32 + lc * 16);
            ldsm_x4(a[0], a[1], a[2], a[3], addr);
        }
#pragma unroll
        for (int np = 0; np < 2; np++) {
            uint32_t b0, b1, b2, b3;
            uint32_t addr = ws_base +
                SW((kc * 16 + lr) * 128 + (chalf * 32 + np * 16 + lc * 8) * 2);
            ldsm_x4_t(b0, b1, b2, b3, addr);
            mma16816(c[2 * np], a, b0, b1);
            mma16816(c[2 * np + 1], a, b2, b3);
        }
    }

    // Epilogue: store h as fp16 (half2 per fragment pair).
    const int qr = lane >> 2;
    const int qc = (lane & 3) * 2;
    long rlo = row0 + rg * 16 + qr;
    long rhi = rlo + 8;
#pragma unroll
    for (int nt = 0; nt < 4; nt++) {
        int col = chalf * 32 + nt * 8 + qc;
        if (rlo < N_NODES) {
            __half2 h = __floats2half2_rn(c[nt][0], c[nt][1]);
            *(__half2*)(g_h + (size_t)rlo * C + col) = h;
        }
        if (rhi < N_NODES) {
            __half2 h = __floats2half2_rn(c[nt][2], c[nt][3]);
            *(__half2*)(g_h + (size_t)rhi * C + col) = h;
        }
    }
}

// ---------------------------------------------------------------------------
// Kernel B: out = segment_sum(h[col]) * deg + bias.
// fp16 gather, depth-2 fp16 tree per 4-edge group, fp32 accumulation.
// Software-pipelined: group g+1's index+gather loads issue before group g's
// reduction, hiding the ~250cyc L2 gather latency.
// 16 lanes/node, 2 nodes/warp, no atomics.
// ---------------------------------------------------------------------------
__global__ __launch_bounds__(256) void agg_kernel(const int* __restrict__ column_index,
                                                  const float* __restrict__ degrees,
                                                  const float* __restrict__ bias,
                                                  float* __restrict__ out) {
    const int warp = (blockIdx.x * blockDim.x + threadIdx.x) >> 5;
    const int lane = threadIdx.x & 31;
    const int half = lane >> 4;
    const int hl = lane & 15;
    const int node = warp * 2 + half;
    if (node >= N_NODES) return;

    const int start = g_row_ptr[node];
    const int end = g_row_ptr[node + 1];
    const int ng = (end - start) >> 2;   // number of full 4-edge groups

    float ax = 0.f, ay = 0.f, az = 0.f, aw = 0.f;

    uint2 c0 = make_uint2(0u, 0u), c1 = c0, c2 = c0, c3 = c0;
    int e = start;

    if (ng > 0) {
        int s0 = __ldg(&column_index[e]);
        int s1 = __ldg(&column_index[e + 1]);
        int s2 = __ldg(&column_index[e + 2]);
        int s3 = __ldg(&column_index[e + 3]);
        c0 = __ldg((const uint2*)(g_h + (size_t)s0 * C) + hl);
        c1 = __ldg((const uint2*)(g_h + (size_t)s1 * C) + hl);
        c2 = __ldg((const uint2*)(g_h + (size_t)s2 * C) + hl);
        c3 = __ldg((const uint2*)(g_h + (size_t)s3 * C) + hl);
    }

    for (int g = 0; g < ng; g++) {
        uint2 n0 = make_uint2(0u, 0u), n1 = n0, n2 = n0, n3 = n0;
        if (g + 1 < ng) {
            int b = e + 4;
            int s0 = __ldg(&column_index[b]);
            int s1 = __ldg(&column_index[b + 1]);
            int s2 = __ldg(&column_index[b + 2]);
            int s3 = __ldg(&column_index[b + 3]);
            n0 = __ldg((const uint2*)(g_h + (size_t)s0 * C) + hl);
            n1 = __ldg((const uint2*)(g_h + (size_t)s1 * C) + hl);
            n2 = __ldg((const uint2*)(g_h + (size_t)s2 * C) + hl);
            n3 = __ldg((const uint2*)(g_h + (size_t)s3 * C) + hl);
        }
        // reduce current group: fp16 pairwise tree, fp32 flush
        __half2 p0 = __hadd2(*(__half2*)&c0.x, *(__half2*)&c1.x);
        __half2 p1 = __hadd2(*(__half2*)&c0.y, *(__half2*)&c1.y);
        __half2 q0 = __hadd2(*(__half2*)&c2.x, *(__half2*)&c3.x);
        __half2 q1 = __hadd2(*(__half2*)&c2.y, *(__half2*)&c3.y);
        __half2 t0 = __hadd2(p0, q0);
        __half2 t1 = __hadd2(p1, q1);
        float2 f0 = __half22float2(t0);
        float2 f1 = __half22float2(t1);
        ax += f0.x; ay += f0.y; az += f1.x; aw += f1.y;

        c0 = n0; c1 = n1; c2 = n2; c3 = n3;
        e += 4;
    }
    // tail: exact fp32 path (<= 3 edges)
    for (; e < end; e++) {
        int s0 = __ldg(&column_index[e]);
        uint2 u = __ldg((const uint2*)(g_h + (size_t)s0 * C) + hl);
        float2 f0 = __half22float2(*(__half2*)&u.x);
        float2 f1 = __half22float2(*(__half2*)&u.y);
        ax += f0.x; ay += f0.y; az += f1.x; aw += f1.y;
    }

    const float d = __ldg(&degrees[node]);
    const float4 b = __ldg((const float4*)bias + hl);
    float4 o;
    o.x = ax * d + b.x;
    o.y = ay * d + b.y;
    o.z = az * d + b.z;
    o.w = aw * d + b.w;
    ((float4*)(out + (size_t)node * C))[hl] = o;
}

// ---------------------------------------------------------------------------
extern "C" void kernel_launch(void* const* d_in, const int* in_sizes, int n_in,
                              void* d_out, int out_size) {
    const float* x            = (const float*)d_in[0];   // [N_NODES, 64]
    const float* weight       = (const float*)d_in[1];   // [64, 64]
    const float* bias         = (const float*)d_in[2];   // [64]
    const int*   column_index = (const int*)d_in[3];     // [N_EDGES]
    const int*   row_index    = (const int*)d_in[4];     // [N_EDGES] sorted
    const float* degrees      = (const float*)d_in[5];   // [N_NODES]
    float* out = (float*)d_out;                          // [N_NODES, 64]

    // A) h = x @ W (fp16, HMMA, 64-row tiles) overlapped with rowptr fill
    transform_kernel<<<RP_B + GEMM_B, 256>>>(x, weight, row_index);

    // B) out = segment_sum(h[col]) * deg + bias  (software-pipelined gather)
    const int warps = (N_NODES + 1) / 2;
    agg_kernel<<<(warps * 32 + 255) / 256, 256>>>(column_index, degrees, bias, out);
}